// round 4
// baseline (speedup 1.0000x reference)
#include <cuda_runtime.h>
#include <cstdint>

// N=50000, E=1600000, F=128, H=128, C=64
#define NMAX 50000
#define EMAX 1600000

// Scratch (no dynamic allocation allowed)
__device__ __align__(16) float g_dinv[NMAX];
__device__ __align__(16) int   g_count[NMAX];
__device__ __align__(16) int   g_rowstart[NMAX + 1];
__device__ __align__(16) int   g_cursor[NMAX];
__device__ __align__(16) int   g_srcs[EMAX];               // edge srcs grouped by dst
__device__ __align__(16) float g_bufA[(size_t)NMAX * 128]; // g1 ; then reused for g2
__device__ __align__(16) float g_bufB[(size_t)NMAX * 128]; // h1f (post-relu)

// ---------------- CSR build ----------------

__global__ void k_zero_int(int* p, int n) {
    int i = blockIdx.x * blockDim.x + threadIdx.x;
    if (i < n) p[i] = 0;
}

// edge_index is int32 (JAX x64-disabled downcasts int64 -> int32)
__global__ void k_hist(const int* __restrict__ dst, int* __restrict__ count, int E, int n) {
    int e = blockIdx.x * blockDim.x + threadIdx.x;
    if (e < E) {
        int d = dst[e];
        if ((unsigned)d < (unsigned)n) atomicAdd(&count[d], 1);
    }
}

// Single-block chunked exclusive scan over count[0..n): rowstart, cursor copy,
// and dinv = rsqrt(count+1) (self-loop included in degree).
__global__ void k_scan(const int* __restrict__ count, int* __restrict__ rowstart,
                       int* __restrict__ cursor, float* __restrict__ dinv, int n) {
    __shared__ int buf[1024];
    __shared__ int carry_s;
    if (threadIdx.x == 0) carry_s = 0;
    __syncthreads();
    for (int base = 0; base < n; base += 1024) {
        int i = base + (int)threadIdx.x;
        int v = (i < n) ? count[i] : 0;
        buf[threadIdx.x] = v;
        __syncthreads();
#pragma unroll
        for (int off = 1; off < 1024; off <<= 1) {
            int t = 0;
            if ((int)threadIdx.x >= off) t = buf[threadIdx.x - off];
            __syncthreads();
            if ((int)threadIdx.x >= off) buf[threadIdx.x] += t;
            __syncthreads();
        }
        int incl = buf[threadIdx.x];
        int carry = carry_s;
        if (i < n) {
            int excl = carry + incl - v;
            rowstart[i] = excl;
            cursor[i]   = excl;
            dinv[i]     = rsqrtf((float)v + 1.0f);
        }
        __syncthreads();
        if (threadIdx.x == 1023) carry_s = carry + incl;
        __syncthreads();
    }
    if (threadIdx.x == 0) rowstart[n] = carry_s;
}

__global__ void k_fill(const int* __restrict__ src, const int* __restrict__ dst,
                       int* __restrict__ cursor, int* __restrict__ srcs, int E, int n) {
    int e = blockIdx.x * blockDim.x + threadIdx.x;
    if (e < E) {
        int d = dst[e];
        int s = src[e];
        if ((unsigned)d < (unsigned)n && (unsigned)s < (unsigned)n) {
            int pos = atomicAdd(&cursor[d], 1);
            srcs[pos] = s;
        }
    }
}

// ---------------- GEMM: out[row][c] = (X[row,:] @ W[:,c]) * dinv[row] ----------------
// K fixed 128. OUTC = 128 or 64. BM=64, BK=16, TM=8, TN=OUTC/32. 256 threads.

template <int OUTC, int TN>
__global__ void k_gemm_scale(const float* __restrict__ X, const float* __restrict__ W,
                             const float* __restrict__ dinv, float* __restrict__ out,
                             int N) {
    constexpr int BM = 64, BK = 16, TM = 8;
    constexpr int TCOLS = OUTC / TN;               // 32
    __shared__ float As[BK * BM];
    __shared__ float Bs[BK * OUTC];

    const int tid = threadIdx.x;
    const int tr = tid / TCOLS;                    // 0..7
    const int tc = tid % TCOLS;                    // 0..31
    const int rowBase = blockIdx.x * BM;

    float acc[TM][TN];
#pragma unroll
    for (int i = 0; i < TM; i++)
#pragma unroll
        for (int j = 0; j < TN; j++) acc[i][j] = 0.f;

    for (int k0 = 0; k0 < 128; k0 += BK) {
        {
            int r = tid >> 2;
            int c4 = tid & 3;
            int row = rowBase + r;
            float4 v = make_float4(0.f, 0.f, 0.f, 0.f);
            if (row < N)
                v = ((const float4*)(X + (size_t)row * 128 + k0))[c4];
            int kb = c4 * 4;
            As[(kb + 0) * BM + r] = v.x;
            As[(kb + 1) * BM + r] = v.y;
            As[(kb + 2) * BM + r] = v.z;
            As[(kb + 3) * BM + r] = v.w;
        }
        {
            constexpr int NV = (BK * OUTC / 4) / 256;
#pragma unroll
            for (int i = 0; i < NV; i++) {
                int idx = tid + i * 256;
                int k = idx / (OUTC / 4);
                int c4 = idx % (OUTC / 4);
                ((float4*)Bs)[idx] = ((const float4*)(W + (size_t)(k0 + k) * OUTC))[c4];
            }
        }
        __syncthreads();

#pragma unroll
        for (int k = 0; k < BK; k++) {
            float a[TM], b[TN];
#pragma unroll
            for (int i = 0; i < TM; i++) a[i] = As[k * BM + tr * TM + i];
#pragma unroll
            for (int j = 0; j < TN; j++) b[j] = Bs[k * OUTC + tc * TN + j];
#pragma unroll
            for (int i = 0; i < TM; i++)
#pragma unroll
                for (int j = 0; j < TN; j++) acc[i][j] += a[i] * b[j];
        }
        __syncthreads();
    }

#pragma unroll
    for (int i = 0; i < TM; i++) {
        int row = rowBase + tr * TM + i;
        if (row < N) {
            float dv = dinv[row];
#pragma unroll
            for (int j = 0; j < TN; j++)
                out[(size_t)row * OUTC + tc * TN + j] = acc[i][j] * dv;
        }
    }
}

// ---------------- gather: per-dst register accumulate, no float atomics ----------------
// One warp per destination node. 128 cols -> float4/lane.
// out[node] = act((sum_{e in CSR(node)} g[srcs[e]] + g[node]) * dinv[node] + bias)

template <bool RELU>
__global__ void k_gather128(const float* __restrict__ g, const int* __restrict__ rowstart,
                            const int* __restrict__ srcs, const float* __restrict__ dinv,
                            const float* __restrict__ bias, float* __restrict__ out, int n) {
    int node = (blockIdx.x * blockDim.x + threadIdx.x) >> 5;
    int lane = threadIdx.x & 31;
    if (node >= n) return;
    int e0 = rowstart[node], e1 = rowstart[node + 1];

    float4 acc = ((const float4*)(g + (size_t)node * 128))[lane];  // self-loop term
    int e = e0;
    while (e < e1) {
        int m = min(32, e1 - e);
        int idx = (lane < m) ? srcs[e + lane] : 0;   // coalesced index batch
#pragma unroll 4
        for (int k = 0; k < m; k++) {
            int s = __shfl_sync(0xffffffffu, idx, k);
            float4 v = ((const float4*)(g + (size_t)s * 128))[lane];
            acc.x += v.x; acc.y += v.y; acc.z += v.z; acc.w += v.w;
        }
        e += m;
    }
    float dv = dinv[node];
    float4 bv = ((const float4*)bias)[lane];
    float4 r;
    r.x = acc.x * dv + bv.x;
    r.y = acc.y * dv + bv.y;
    r.z = acc.z * dv + bv.z;
    r.w = acc.w * dv + bv.w;
    if (RELU) {
        r.x = fmaxf(r.x, 0.f); r.y = fmaxf(r.y, 0.f);
        r.z = fmaxf(r.z, 0.f); r.w = fmaxf(r.w, 0.f);
    }
    ((float4*)(out + (size_t)node * 128))[lane] = r;
}

// 64 cols -> float2/lane, no relu
__global__ void k_gather64(const float* __restrict__ g, const int* __restrict__ rowstart,
                           const int* __restrict__ srcs, const float* __restrict__ dinv,
                           const float* __restrict__ bias, float* __restrict__ out, int n) {
    int node = (blockIdx.x * blockDim.x + threadIdx.x) >> 5;
    int lane = threadIdx.x & 31;
    if (node >= n) return;
    int e0 = rowstart[node], e1 = rowstart[node + 1];

    float2 acc = ((const float2*)(g + (size_t)node * 64))[lane];   // self-loop term
    int e = e0;
    while (e < e1) {
        int m = min(32, e1 - e);
        int idx = (lane < m) ? srcs[e + lane] : 0;
#pragma unroll 4
        for (int k = 0; k < m; k++) {
            int s = __shfl_sync(0xffffffffu, idx, k);
            float2 v = ((const float2*)(g + (size_t)s * 64))[lane];
            acc.x += v.x; acc.y += v.y;
        }
        e += m;
    }
    float dv = dinv[node];
    float2 bv = ((const float2*)bias)[lane];
    float2 r;
    r.x = acc.x * dv + bv.x;
    r.y = acc.y * dv + bv.y;
    ((float2*)(out + (size_t)node * 64))[lane] = r;
}

// ---------------- launch ----------------

extern "C" void kernel_launch(void* const* d_in, const int* in_sizes, int n_in,
                              void* d_out, int out_size) {
    const float* x   = (const float*)d_in[0];
    const int*   ei  = (const int*)d_in[1];    // int32! (JAX x64 disabled)
    const float* W1  = (const float*)d_in[2];
    const float* b1  = (const float*)d_in[3];
    const float* W2  = (const float*)d_in[4];
    const float* b2  = (const float*)d_in[5];
    float*       out = (float*)d_out;

    const int N = in_sizes[0] / 128;
    const int E = in_sizes[1] / 2;
    const int* srcp = ei;
    const int* dstp = ei + E;

    float* dinv;   cudaGetSymbolAddress((void**)&dinv,   g_dinv);
    int*   count;  cudaGetSymbolAddress((void**)&count,  g_count);
    int*   rowst;  cudaGetSymbolAddress((void**)&rowst,  g_rowstart);
    int*   cursor; cudaGetSymbolAddress((void**)&cursor, g_cursor);
    int*   srcs;   cudaGetSymbolAddress((void**)&srcs,   g_srcs);
    float* bufA;   cudaGetSymbolAddress((void**)&bufA,   g_bufA);
    float* bufB;   cudaGetSymbolAddress((void**)&bufB,   g_bufB);

    const int T = 256;

    // CSR build (group edges by dst) + dinv
    k_zero_int<<<(N + T - 1) / T, T>>>(count, N);
    k_hist<<<(E + T - 1) / T, T>>>(dstp, count, E, N);
    k_scan<<<1, 1024>>>(count, rowst, cursor, dinv, N);
    k_fill<<<(E + T - 1) / T, T>>>(srcp, dstp, cursor, srcs, E, N);

    // layer 1: g1 = (x@W1)*dinv -> bufA ; h1f = relu(gather(g1)+bias) -> bufB
    k_gemm_scale<128, 4><<<(N + 63) / 64, 256>>>(x, W1, dinv, bufA, N);
    k_gather128<true><<<(N * 32 + T - 1) / T, T>>>(bufA, rowst, srcs, dinv, b1, bufB, N);

    // layer 2: g2 = (h1f@W2)*dinv -> bufA ; out = gather(g2)+bias
    k_gemm_scale<64, 2><<<(N + 63) / 64, 256>>>(bufB, W2, dinv, bufA, N);
    k_gather64<<<(N * 32 + T - 1) / T, T>>>(bufA, rowst, srcs, dinv, b2, out, N);
}

// round 5
// speedup vs baseline: 1.3174x; 1.3174x over previous
#include <cuda_runtime.h>
#include <cstdint>

// N=50000, E=1600000, F=128, H=128, C=64
#define NMAX 50000
#define EMAX 1600000
#define SCAN_B 1024

// Scratch (no dynamic allocation allowed)
__device__ __align__(16) float g_dinv[NMAX];
__device__ __align__(16) int   g_count[NMAX];
__device__ __align__(16) int   g_rowstart[NMAX + 1];
__device__ __align__(16) int   g_rank[EMAX];               // per-edge slot within its dst bucket
__device__ __align__(16) int   g_blocksum[(NMAX + SCAN_B - 1) / SCAN_B + 1];
__device__ __align__(16) int   g_srcs[EMAX];               // edge srcs grouped by dst
__device__ __align__(16) float g_bufA[(size_t)NMAX * 128]; // g1 ; then reused for g2
__device__ __align__(16) float g_bufB[(size_t)NMAX * 128]; // h1f (post-relu)

// ---------------- CSR build ----------------

__global__ void k_zero_int(int* p, int n) {
    int i = blockIdx.x * blockDim.x + threadIdx.x;
    if (i < n) p[i] = 0;
}

// rank[e] = old count of dst bucket (gives each edge a unique slot, no 2nd atomic pass)
__global__ void k_hist(const int* __restrict__ dst, int* __restrict__ count,
                       int* __restrict__ rank, int E, int n) {
    int e = blockIdx.x * blockDim.x + threadIdx.x;
    if (e < E) {
        int d = dst[e];
        int r = 0;
        if ((unsigned)d < (unsigned)n) r = atomicAdd(&count[d], 1);
        rank[e] = r;
    }
}

// scan stage 1: per-block exclusive scan of count -> rowstart (local), block total -> blocksum
__global__ void k_scan1(const int* __restrict__ count, int* __restrict__ rowstart,
                        int* __restrict__ blocksum, int n) {
    __shared__ int buf[SCAN_B];
    int i = blockIdx.x * SCAN_B + threadIdx.x;
    int v = (i < n) ? count[i] : 0;
    buf[threadIdx.x] = v;
    __syncthreads();
#pragma unroll
    for (int off = 1; off < SCAN_B; off <<= 1) {
        int t = 0;
        if ((int)threadIdx.x >= off) t = buf[threadIdx.x - off];
        __syncthreads();
        if ((int)threadIdx.x >= off) buf[threadIdx.x] += t;
        __syncthreads();
    }
    if (i < n) rowstart[i] = buf[threadIdx.x] - v;   // local exclusive
    if (threadIdx.x == SCAN_B - 1) blocksum[blockIdx.x] = buf[SCAN_B - 1];
}

// scan stage 2: exclusive scan of block sums (nb <= 1024)
__global__ void k_scan2(int* __restrict__ blocksum, int nb) {
    __shared__ int buf[SCAN_B];
    int v = (threadIdx.x < (unsigned)nb) ? blocksum[threadIdx.x] : 0;
    buf[threadIdx.x] = v;
    __syncthreads();
#pragma unroll
    for (int off = 1; off < SCAN_B; off <<= 1) {
        int t = 0;
        if ((int)threadIdx.x >= off) t = buf[threadIdx.x - off];
        __syncthreads();
        if ((int)threadIdx.x >= off) buf[threadIdx.x] += t;
        __syncthreads();
    }
    if (threadIdx.x < (unsigned)nb) blocksum[threadIdx.x] = buf[threadIdx.x] - v;
}

// scan stage 3: add block offsets, produce dinv; rowstart[n] = E
__global__ void k_scan3(const int* __restrict__ count, int* __restrict__ rowstart,
                        const int* __restrict__ blocksum, float* __restrict__ dinv,
                        int n, int E) {
    int i = blockIdx.x * blockDim.x + threadIdx.x;
    if (i < n) {
        rowstart[i] += blocksum[i / SCAN_B];
        dinv[i] = rsqrtf((float)count[i] + 1.0f);
    }
    if (i == 0) rowstart[n] = E;
}

// atomic-free fill: pos = rowstart[dst] + rank[e]
__global__ void k_fill(const int* __restrict__ src, const int* __restrict__ dst,
                       const int* __restrict__ rowstart, const int* __restrict__ rank,
                       int* __restrict__ srcs, int E, int n) {
    int e = blockIdx.x * blockDim.x + threadIdx.x;
    if (e < E) {
        int d = dst[e];
        int s = src[e];
        if ((unsigned)d < (unsigned)n && (unsigned)s < (unsigned)n)
            srcs[rowstart[d] + rank[e]] = s;
    }
}

// ---------------- GEMM: out[row][c] = (X[row,:] @ W[:,c]) * dinv[row] ----------------
// K fixed 128. BM=128, BN=OUTC (128 or 64), BK=8. 256 threads, microtile TM=8 x TN=OUTC/16.

template <int OUTC, int TN>
__global__ void k_gemm_scale(const float* __restrict__ X, const float* __restrict__ W,
                             const float* __restrict__ dinv, float* __restrict__ out,
                             int N) {
    constexpr int BM = 128, BK = 8, TM = 8;
    constexpr int TCOLS = OUTC / TN;               // 16
    __shared__ float As[BK * BM];                  // As[k][r]
    __shared__ float Bs[BK * OUTC];                // Bs[k][c]

    const int tid = threadIdx.x;                   // 0..255
    const int tr = tid / TCOLS;                    // 0..15
    const int tc = tid % TCOLS;                    // 0..15
    const int rowBase = blockIdx.x * BM;

    float acc[TM][TN];
#pragma unroll
    for (int i = 0; i < TM; i++)
#pragma unroll
        for (int j = 0; j < TN; j++) acc[i][j] = 0.f;

    for (int k0 = 0; k0 < 128; k0 += BK) {
        // A tile: 128 rows x 8 k = 256 float4 (one per thread), store transposed
        {
            int r = tid >> 1;                      // 0..127
            int c4 = tid & 1;                      // which float4 of the 8 k's
            int row = rowBase + r;
            float4 v = make_float4(0.f, 0.f, 0.f, 0.f);
            if (row < N)
                v = ((const float4*)(X + (size_t)row * 128 + k0))[c4];
            int kb = c4 * 4;
            As[(kb + 0) * BM + r] = v.x;
            As[(kb + 1) * BM + r] = v.y;
            As[(kb + 2) * BM + r] = v.z;
            As[(kb + 3) * BM + r] = v.w;
        }
        // B tile: 8 k x OUTC floats
        {
            constexpr int NV4 = BK * OUTC / 4;     // 256 (OUTC=128) or 128 (OUTC=64)
            if (NV4 == 256 || tid < NV4) {
                int k  = tid / (OUTC / 4);
                int c4 = tid % (OUTC / 4);
                ((float4*)Bs)[tid] = ((const float4*)(W + (size_t)(k0 + k) * OUTC))[c4];
            }
        }
        __syncthreads();

#pragma unroll
        for (int k = 0; k < BK; k++) {
            float a[TM], b[TN];
#pragma unroll
            for (int i = 0; i < TM; i++) a[i] = As[k * BM + tr * TM + i];
#pragma unroll
            for (int j = 0; j < TN; j++) b[j] = Bs[k * OUTC + tc * TN + j];
#pragma unroll
            for (int i = 0; i < TM; i++)
#pragma unroll
                for (int j = 0; j < TN; j++) acc[i][j] += a[i] * b[j];
        }
        __syncthreads();
    }

#pragma unroll
    for (int i = 0; i < TM; i++) {
        int row = rowBase + tr * TM + i;
        if (row < N) {
            float dv = dinv[row];
#pragma unroll
            for (int j4 = 0; j4 < TN / 4; j4++) {
                float4 v;
                v.x = acc[i][j4 * 4 + 0] * dv;
                v.y = acc[i][j4 * 4 + 1] * dv;
                v.z = acc[i][j4 * 4 + 2] * dv;
                v.w = acc[i][j4 * 4 + 3] * dv;
                ((float4*)(out + (size_t)row * OUTC + tc * TN))[j4] = v;
            }
        }
    }
}

// ---------------- gather: per-dst register accumulate, no float atomics ----------------

template <bool RELU>
__global__ void k_gather128(const float* __restrict__ g, const int* __restrict__ rowstart,
                            const int* __restrict__ srcs, const float* __restrict__ dinv,
                            const float* __restrict__ bias, float* __restrict__ out, int n) {
    int node = (blockIdx.x * blockDim.x + threadIdx.x) >> 5;
    int lane = threadIdx.x & 31;
    if (node >= n) return;
    int e0 = rowstart[node], e1 = rowstart[node + 1];

    float4 acc = ((const float4*)(g + (size_t)node * 128))[lane];  // self-loop term
    int e = e0;
    while (e < e1) {
        int m = min(32, e1 - e);
        int idx = (lane < m) ? srcs[e + lane] : 0;   // coalesced index batch
#pragma unroll 4
        for (int k = 0; k < m; k++) {
            int s = __shfl_sync(0xffffffffu, idx, k);
            float4 v = ((const float4*)(g + (size_t)s * 128))[lane];
            acc.x += v.x; acc.y += v.y; acc.z += v.z; acc.w += v.w;
        }
        e += m;
    }
    float dv = dinv[node];
    float4 bv = ((const float4*)bias)[lane];
    float4 r;
    r.x = acc.x * dv + bv.x;
    r.y = acc.y * dv + bv.y;
    r.z = acc.z * dv + bv.z;
    r.w = acc.w * dv + bv.w;
    if (RELU) {
        r.x = fmaxf(r.x, 0.f); r.y = fmaxf(r.y, 0.f);
        r.z = fmaxf(r.z, 0.f); r.w = fmaxf(r.w, 0.f);
    }
    ((float4*)(out + (size_t)node * 128))[lane] = r;
}

__global__ void k_gather64(const float* __restrict__ g, const int* __restrict__ rowstart,
                           const int* __restrict__ srcs, const float* __restrict__ dinv,
                           const float* __restrict__ bias, float* __restrict__ out, int n) {
    int node = (blockIdx.x * blockDim.x + threadIdx.x) >> 5;
    int lane = threadIdx.x & 31;
    if (node >= n) return;
    int e0 = rowstart[node], e1 = rowstart[node + 1];

    float2 acc = ((const float2*)(g + (size_t)node * 64))[lane];   // self-loop term
    int e = e0;
    while (e < e1) {
        int m = min(32, e1 - e);
        int idx = (lane < m) ? srcs[e + lane] : 0;
#pragma unroll 4
        for (int k = 0; k < m; k++) {
            int s = __shfl_sync(0xffffffffu, idx, k);
            float2 v = ((const float2*)(g + (size_t)s * 64))[lane];
            acc.x += v.x; acc.y += v.y;
        }
        e += m;
    }
    float dv = dinv[node];
    float2 bv = ((const float2*)bias)[lane];
    float2 r;
    r.x = acc.x * dv + bv.x;
    r.y = acc.y * dv + bv.y;
    ((float2*)(out + (size_t)node * 64))[lane] = r;
}

// ---------------- launch ----------------

extern "C" void kernel_launch(void* const* d_in, const int* in_sizes, int n_in,
                              void* d_out, int out_size) {
    const float* x   = (const float*)d_in[0];
    const int*   ei  = (const int*)d_in[1];    // int32 (JAX x64 disabled)
    const float* W1  = (const float*)d_in[2];
    const float* b1  = (const float*)d_in[3];
    const float* W2  = (const float*)d_in[4];
    const float* b2  = (const float*)d_in[5];
    float*       out = (float*)d_out;

    const int N = in_sizes[0] / 128;
    const int E = in_sizes[1] / 2;
    const int* srcp = ei;
    const int* dstp = ei + E;

    float* dinv;  cudaGetSymbolAddress((void**)&dinv,  g_dinv);
    int*   count; cudaGetSymbolAddress((void**)&count, g_count);
    int*   rowst; cudaGetSymbolAddress((void**)&rowst, g_rowstart);
    int*   rank;  cudaGetSymbolAddress((void**)&rank,  g_rank);
    int*   bsum;  cudaGetSymbolAddress((void**)&bsum,  g_blocksum);
    int*   srcs;  cudaGetSymbolAddress((void**)&srcs,  g_srcs);
    float* bufA;  cudaGetSymbolAddress((void**)&bufA,  g_bufA);
    float* bufB;  cudaGetSymbolAddress((void**)&bufB,  g_bufB);

    const int T = 256;
    const int nb = (N + SCAN_B - 1) / SCAN_B;   // 49

    // CSR build (group edges by dst) + dinv
    k_zero_int<<<(N + T - 1) / T, T>>>(count, N);
    k_hist<<<(E + T - 1) / T, T>>>(dstp, count, rank, E, N);
    k_scan1<<<nb, SCAN_B>>>(count, rowst, bsum, N);
    k_scan2<<<1, SCAN_B>>>(bsum, nb);
    k_scan3<<<(N + T - 1) / T, T>>>(count, rowst, bsum, dinv, N, E);
    k_fill<<<(E + T - 1) / T, T>>>(srcp, dstp, rowst, rank, srcs, E, N);

    // layer 1: g1 = (x@W1)*dinv -> bufA ; h1f = relu(gather(g1)+bias) -> bufB
    k_gemm_scale<128, 8><<<(N + 127) / 128, 256>>>(x, W1, dinv, bufA, N);
    k_gather128<true><<<(N * 32 + T - 1) / T, T>>>(bufA, rowst, srcs, dinv, b1, bufB, N);

    // layer 2: g2 = (h1f@W2)*dinv -> bufA ; out = gather(g2)+bias
    k_gemm_scale<64, 4><<<(N + 127) / 128, 256>>>(bufB, W2, dinv, bufA, N);
    k_gather64<<<(N * 32 + T - 1) / T, T>>>(bufA, rowst, srcs, dinv, b2, out, N);
}

// round 6
// speedup vs baseline: 1.4460x; 1.0976x over previous
#include <cuda_runtime.h>
#include <cuda_fp16.h>
#include <cstdint>

// N=50000, E=1600000, F=128, H=128, C=64
#define NMAX 50000
#define EMAX 1600000
#define SCAN_B 1024

// Scratch (no dynamic allocation allowed)
__device__ __align__(16) float  g_dinv[NMAX];
__device__ __align__(16) int    g_count[NMAX];
__device__ __align__(16) int    g_rowstart[NMAX + 1];
__device__ __align__(16) int    g_rank[EMAX];
__device__ __align__(16) int    g_blocksum[(NMAX + SCAN_B - 1) / SCAN_B + 1];
__device__ __align__(16) int    g_srcs[EMAX];                 // edge srcs grouped by dst
__device__ __align__(16) __half g_msg[(size_t)NMAX * 128];    // fp16 messages (g1, then g2)
__device__ __align__(16) float  g_h1f[(size_t)NMAX * 128];    // h1f (post-relu, fp32)

// ---------------- CSR build ----------------

__global__ void k_zero_int(int* p, int n) {
    int i = blockIdx.x * blockDim.x + threadIdx.x;
    if (i < n) p[i] = 0;
}

__global__ void k_hist(const int* __restrict__ dst, int* __restrict__ count,
                       int* __restrict__ rank, int E, int n) {
    int e = blockIdx.x * blockDim.x + threadIdx.x;
    if (e < E) {
        int d = dst[e];
        int r = 0;
        if ((unsigned)d < (unsigned)n) r = atomicAdd(&count[d], 1);
        rank[e] = r;
    }
}

__global__ void k_scan1(const int* __restrict__ count, int* __restrict__ rowstart,
                        int* __restrict__ blocksum, int n) {
    __shared__ int buf[SCAN_B];
    int i = blockIdx.x * SCAN_B + threadIdx.x;
    int v = (i < n) ? count[i] : 0;
    buf[threadIdx.x] = v;
    __syncthreads();
#pragma unroll
    for (int off = 1; off < SCAN_B; off <<= 1) {
        int t = 0;
        if ((int)threadIdx.x >= off) t = buf[threadIdx.x - off];
        __syncthreads();
        if ((int)threadIdx.x >= off) buf[threadIdx.x] += t;
        __syncthreads();
    }
    if (i < n) rowstart[i] = buf[threadIdx.x] - v;
    if (threadIdx.x == SCAN_B - 1) blocksum[blockIdx.x] = buf[SCAN_B - 1];
}

__global__ void k_scan2(int* __restrict__ blocksum, int nb) {
    __shared__ int buf[SCAN_B];
    int v = (threadIdx.x < (unsigned)nb) ? blocksum[threadIdx.x] : 0;
    buf[threadIdx.x] = v;
    __syncthreads();
#pragma unroll
    for (int off = 1; off < SCAN_B; off <<= 1) {
        int t = 0;
        if ((int)threadIdx.x >= off) t = buf[threadIdx.x - off];
        __syncthreads();
        if ((int)threadIdx.x >= off) buf[threadIdx.x] += t;
        __syncthreads();
    }
    if (threadIdx.x < (unsigned)nb) blocksum[threadIdx.x] = buf[threadIdx.x] - v;
}

__global__ void k_scan3(const int* __restrict__ count, int* __restrict__ rowstart,
                        const int* __restrict__ blocksum, float* __restrict__ dinv,
                        int n, int E) {
    int i = blockIdx.x * blockDim.x + threadIdx.x;
    if (i < n) {
        rowstart[i] += blocksum[i / SCAN_B];
        dinv[i] = rsqrtf((float)count[i] + 1.0f);
    }
    if (i == 0) rowstart[n] = E;
}

__global__ void k_fill(const int* __restrict__ src, const int* __restrict__ dst,
                       const int* __restrict__ rowstart, const int* __restrict__ rank,
                       int* __restrict__ srcs, int E, int n) {
    int e = blockIdx.x * blockDim.x + threadIdx.x;
    if (e < E) {
        int d = dst[e];
        int s = src[e];
        if ((unsigned)d < (unsigned)n && (unsigned)s < (unsigned)n)
            srcs[rowstart[d] + rank[e]] = s;
    }
}

// ---------------- GEMM: msg[row][c] = half((X[row,:] @ W[:,c]) * dinv[row]) ----------------
// K fixed 128. BM=128, BN=OUTC, BK=8, 256 threads, TM=8 x TN=OUTC/16. fp16 output.

template <int OUTC, int TN>
__global__ void k_gemm_scale_h(const float* __restrict__ X, const float* __restrict__ W,
                               const float* __restrict__ dinv, __half* __restrict__ out,
                               int N) {
    constexpr int BM = 128, BK = 8, TM = 8;
    constexpr int TCOLS = OUTC / TN;               // 16
    __shared__ float As[BK * BM];
    __shared__ float Bs[BK * OUTC];

    const int tid = threadIdx.x;
    const int tr = tid / TCOLS;
    const int tc = tid % TCOLS;
    const int rowBase = blockIdx.x * BM;

    float acc[TM][TN];
#pragma unroll
    for (int i = 0; i < TM; i++)
#pragma unroll
        for (int j = 0; j < TN; j++) acc[i][j] = 0.f;

    for (int k0 = 0; k0 < 128; k0 += BK) {
        {
            int r = tid >> 1;
            int c4 = tid & 1;
            int row = rowBase + r;
            float4 v = make_float4(0.f, 0.f, 0.f, 0.f);
            if (row < N)
                v = ((const float4*)(X + (size_t)row * 128 + k0))[c4];
            int kb = c4 * 4;
            As[(kb + 0) * BM + r] = v.x;
            As[(kb + 1) * BM + r] = v.y;
            As[(kb + 2) * BM + r] = v.z;
            As[(kb + 3) * BM + r] = v.w;
        }
        {
            constexpr int NV4 = BK * OUTC / 4;     // 256 or 128
            if (NV4 == 256 || tid < NV4) {
                int k  = tid / (OUTC / 4);
                int c4 = tid % (OUTC / 4);
                ((float4*)Bs)[tid] = ((const float4*)(W + (size_t)(k0 + k) * OUTC))[c4];
            }
        }
        __syncthreads();

#pragma unroll
        for (int k = 0; k < BK; k++) {
            float a[TM], b[TN];
#pragma unroll
            for (int i = 0; i < TM; i++) a[i] = As[k * BM + tr * TM + i];
#pragma unroll
            for (int j = 0; j < TN; j++) b[j] = Bs[k * OUTC + tc * TN + j];
#pragma unroll
            for (int i = 0; i < TM; i++)
#pragma unroll
                for (int j = 0; j < TN; j++) acc[i][j] += a[i] * b[j];
        }
        __syncthreads();
    }

#pragma unroll
    for (int i = 0; i < TM; i++) {
        int row = rowBase + tr * TM + i;
        if (row < N) {
            float dv = dinv[row];
            __half2 hv[TN / 2];
#pragma unroll
            for (int j2 = 0; j2 < TN / 2; j2++)
                hv[j2] = __floats2half2_rn(acc[i][j2 * 2] * dv, acc[i][j2 * 2 + 1] * dv);
            // TN=8 -> one 16B store; TN=4 -> one 8B store
            if (TN == 8)
                *((uint4*)(out + (size_t)row * OUTC + tc * TN)) = *((uint4*)hv);
            else
                *((uint2*)(out + (size_t)row * OUTC + tc * TN)) = *((uint2*)hv);
        }
    }
}

// ---------------- gathers: fp16 messages, fp32 accumulate ----------------
// Layer 1: one warp per node, lane covers 4 of 128 cols (uint2 = 4 halves / 8B).
// h1f[node] = relu((sum msg[src] + msg[node]) * dinv[node] + b1)   (fp32 out)

__global__ void k_gather128h(const __half* __restrict__ g, const int* __restrict__ rowstart,
                             const int* __restrict__ srcs, const float* __restrict__ dinv,
                             const float* __restrict__ bias, float* __restrict__ out, int n) {
    int node = (blockIdx.x * blockDim.x + threadIdx.x) >> 5;
    int lane = threadIdx.x & 31;
    if (node >= n) return;
    int e0 = rowstart[node], e1 = rowstart[node + 1];

    // self-loop term
    float acc0, acc1, acc2, acc3;
    {
        uint2 u = *((const uint2*)(g + (size_t)node * 128 + lane * 4));
        float2 a = __half22float2(*(const __half2*)&u.x);
        float2 b = __half22float2(*(const __half2*)&u.y);
        acc0 = a.x; acc1 = a.y; acc2 = b.x; acc3 = b.y;
    }
    int e = e0;
    while (e < e1) {
        int m = min(32, e1 - e);
        int idx = (lane < m) ? srcs[e + lane] : 0;
#pragma unroll 4
        for (int k = 0; k < m; k++) {
            int s = __shfl_sync(0xffffffffu, idx, k);
            uint2 u = *((const uint2*)(g + (size_t)s * 128 + lane * 4));
            float2 a = __half22float2(*(const __half2*)&u.x);
            float2 b = __half22float2(*(const __half2*)&u.y);
            acc0 += a.x; acc1 += a.y; acc2 += b.x; acc3 += b.y;
        }
        e += m;
    }
    float dv = dinv[node];
    float4 bv = ((const float4*)bias)[lane];
    float4 r;
    r.x = fmaxf(acc0 * dv + bv.x, 0.f);
    r.y = fmaxf(acc1 * dv + bv.y, 0.f);
    r.z = fmaxf(acc2 * dv + bv.z, 0.f);
    r.w = fmaxf(acc3 * dv + bv.w, 0.f);
    ((float4*)(out + (size_t)node * 128))[lane] = r;
}

// Layer 2: 64 cols, lane covers 2 cols (half2 / 4B). fp32 out, no relu.
__global__ void k_gather64h(const __half* __restrict__ g, const int* __restrict__ rowstart,
                            const int* __restrict__ srcs, const float* __restrict__ dinv,
                            const float* __restrict__ bias, float* __restrict__ out, int n) {
    int node = (blockIdx.x * blockDim.x + threadIdx.x) >> 5;
    int lane = threadIdx.x & 31;
    if (node >= n) return;
    int e0 = rowstart[node], e1 = rowstart[node + 1];

    float2 acc = __half22float2(*((const __half2*)(g + (size_t)node * 64 + lane * 2)));
    int e = e0;
    while (e < e1) {
        int m = min(32, e1 - e);
        int idx = (lane < m) ? srcs[e + lane] : 0;
#pragma unroll 4
        for (int k = 0; k < m; k++) {
            int s = __shfl_sync(0xffffffffu, idx, k);
            float2 v = __half22float2(*((const __half2*)(g + (size_t)s * 64 + lane * 2)));
            acc.x += v.x; acc.y += v.y;
        }
        e += m;
    }
    float dv = dinv[node];
    float2 bv = ((const float2*)bias)[lane];
    float2 r;
    r.x = acc.x * dv + bv.x;
    r.y = acc.y * dv + bv.y;
    ((float2*)(out + (size_t)node * 64))[lane] = r;
}

// ---------------- launch ----------------

extern "C" void kernel_launch(void* const* d_in, const int* in_sizes, int n_in,
                              void* d_out, int out_size) {
    const float* x   = (const float*)d_in[0];
    const int*   ei  = (const int*)d_in[1];    // int32 (JAX x64 disabled)
    const float* W1  = (const float*)d_in[2];
    const float* b1  = (const float*)d_in[3];
    const float* W2  = (const float*)d_in[4];
    const float* b2  = (const float*)d_in[5];
    float*       out = (float*)d_out;

    const int N = in_sizes[0] / 128;
    const int E = in_sizes[1] / 2;
    const int* srcp = ei;
    const int* dstp = ei + E;

    float*  dinv;  cudaGetSymbolAddress((void**)&dinv,  g_dinv);
    int*    count; cudaGetSymbolAddress((void**)&count, g_count);
    int*    rowst; cudaGetSymbolAddress((void**)&rowst, g_rowstart);
    int*    rank;  cudaGetSymbolAddress((void**)&rank,  g_rank);
    int*    bsum;  cudaGetSymbolAddress((void**)&bsum,  g_blocksum);
    int*    srcs;  cudaGetSymbolAddress((void**)&srcs,  g_srcs);
    __half* msg;   cudaGetSymbolAddress((void**)&msg,   g_msg);
    float*  h1f;   cudaGetSymbolAddress((void**)&h1f,   g_h1f);

    const int T = 256;
    const int nb = (N + SCAN_B - 1) / SCAN_B;

    // CSR build (group edges by dst) + dinv
    k_zero_int<<<(N + T - 1) / T, T>>>(count, N);
    k_hist<<<(E + T - 1) / T, T>>>(dstp, count, rank, E, N);
    k_scan1<<<nb, SCAN_B>>>(count, rowst, bsum, N);
    k_scan2<<<1, SCAN_B>>>(bsum, nb);
    k_scan3<<<(N + T - 1) / T, T>>>(count, rowst, bsum, dinv, N, E);
    k_fill<<<(E + T - 1) / T, T>>>(srcp, dstp, rowst, rank, srcs, E, N);

    // layer 1: g1 = half((x@W1)*dinv) -> msg ; h1f = relu(gather(g1)+b1) -> h1f (fp32)
    k_gemm_scale_h<128, 8><<<(N + 127) / 128, 256>>>(x, W1, dinv, msg, N);
    k_gather128h<<<(N * 32 + T - 1) / T, T>>>(msg, rowst, srcs, dinv, b1, h1f, N);

    // layer 2: g2 = half((h1f@W2)*dinv) -> msg ; out = gather(g2)+b2 (fp32)
    k_gemm_scale_h<64, 4><<<(N + 127) / 128, 256>>>(h1f, W2, dinv, msg, N);
    k_gather64h<<<(N * 32 + T - 1) / T, T>>>(msg, rowst, srcs, dinv, b2, out, N);
}